// round 10
// baseline (speedup 1.0000x reference)
#include <cuda_runtime.h>

#define NQ    14
#define NL    6
#define BATCH 1024
#define NSITE 8192            // 2^13 pack sites (pack dim = wire 13), 16B each
#define TPB   1024

typedef unsigned long long ull;

// ---------------- f32x2 packed helpers ----------------
__device__ __forceinline__ ull f2mul(ull a, ull b) {
    ull d; asm("mul.rn.f32x2 %0,%1,%2;" : "=l"(d) : "l"(a), "l"(b)); return d;
}
__device__ __forceinline__ ull f2fma(ull a, ull b, ull c) {
    ull d; asm("fma.rn.f32x2 %0,%1,%2,%3;" : "=l"(d) : "l"(a), "l"(b), "l"(c)); return d;
}
__device__ __forceinline__ ull pk2(float lo, float hi) {
    ull d; asm("mov.b64 %0,{%1,%2};" : "=l"(d) : "f"(lo), "f"(hi)); return d;
}
__device__ __forceinline__ ull dup2(float v) {
    ull d; asm("mov.b64 %0,{%1,%1};" : "=l"(d) : "f"(v)); return d;
}
__device__ __forceinline__ ull swap2(ull v) {
    ull d;
    asm("{ .reg .b32 lo,hi; mov.b64 {lo,hi},%1; mov.b64 %0,{hi,lo}; }"
        : "=l"(d) : "l"(v));
    return d;
}

// ---------------- layout maps (GF(2)-linear) ----------------
// site z (13 bits = wires 0..12) -> physical site (bank swizzle)
// conflict-free for all 5 pass layouts (low-3 bits distinct per LDS.128 phase)
__host__ __device__ __forceinline__ unsigned psite(unsigned z) {
    return z ^ ((z >> 3) & 7u);
}
// 14-bit state x -> physical float index of Re(amp): site*4 | wire13 (Im = +2)
__host__ __device__ __forceinline__ unsigned famp(unsigned x) {
    return (psite(x & 8191u) << 2) | ((x >> 13) & 1u);
}

// ---------------- precomputed tables ----------------
__device__ ull      d_gpk[NL][13][12];
__device__ ull      d_gin[NL][6];
__device__ unsigned d_qf[NL][NQ];

__global__ void setup_kernel(const float* __restrict__ w) {
    const int tid = threadIdx.x;
    if (tid < NL * NQ) {
        const int l = tid / NQ, q = tid % NQ;
        const float phi = w[tid * 3 + 0];
        const float th  = w[tid * 3 + 1];
        const float om  = w[tid * 3 + 2];
        float cth, sth, ca, sa, cb, sb;
        sincosf(0.5f * th, &sth, &cth);
        sincosf(0.5f * (phi + om), &sa, &ca);
        sincosf(0.5f * (phi - om), &sb, &cb);
        // Rot = RZ(om) RY(th) RZ(phi)
        const float g00r =  cth * ca, g00i = -cth * sa;
        const float g01r = -sth * cb, g01i = -sth * sb;
        const float g10r =  sth * cb, g10i = -sth * sb;
        const float g11r =  cth * ca, g11i =  cth * sa;
        if (q < 13) {
            ull* g = d_gpk[l][q];
            g[0]  = dup2(g00r); g[1]  = dup2(g00i); g[2]  = dup2(-g00i);
            g[3]  = dup2(g01r); g[4]  = dup2(g01i); g[5]  = dup2(-g01i);
            g[6]  = dup2(g10r); g[7]  = dup2(g10i); g[8]  = dup2(-g10i);
            g[9]  = dup2(g11r); g[10] = dup2(g11i); g[11] = dup2(-g11i);
        } else {
            ull* K = d_gin[l];
            K[0] = pk2(g00r, g11r);  K[1] = pk2(g00i, g11i);
            K[2] = pk2(-g00i, -g11i);
            K[3] = pk2(g01r, g10r);  K[4] = pk2(g01i, g10i);
            K[5] = pk2(-g01i, -g10i);
        }
    } else if (tid >= 128 && tid < 128 + NL * NQ) {
        const int id = tid - 128;
        const int l = id / NQ, b = id % NQ;
        const int rr = (l % (NQ - 1)) + 1;
        unsigned y = 1u << b;
        for (int ww = NQ - 1; ww >= 0; ww--) {
            const unsigned bit = (y >> ww) & 1u;
            y ^= bit << ((ww + rr) % NQ);
        }
        d_qf[l][b] = famp(y);
    }
}

// ---------------- packed 2x2 gate on pack-index bit P (8 packs) ----------------
template <int P>
__device__ __forceinline__ void pgate(ull* re, ull* im, const ull* gg) {
    const ull g0 = gg[0], g1 = gg[1], g2 = gg[2], g3 = gg[3], g4 = gg[4], g5 = gg[5];
    const ull g6 = gg[6], g7 = gg[7], g8 = gg[8], g9 = gg[9], g10 = gg[10], g11 = gg[11];
#pragma unroll
    for (int base = 0; base < 8; base++) {
        if (base & (1 << P)) continue;
        const int hi = base | (1 << P);
        const ull are = re[base], aim = im[base], bre = re[hi], bim = im[hi];
        re[base] = f2fma(g5,  bim, f2fma(g3, bre, f2fma(g2, aim, f2mul(g0, are))));
        im[base] = f2fma(g4,  bre, f2fma(g3, bim, f2fma(g1, are, f2mul(g0, aim))));
        re[hi]   = f2fma(g11, bim, f2fma(g9, bre, f2fma(g8, aim, f2mul(g6, are))));
        im[hi]   = f2fma(g10, bre, f2fma(g9, bim, f2fma(g7, are, f2mul(g6, aim))));
    }
}

// intra-pack gate (pack dimension = wire 13), 8 packs
__device__ __forceinline__ void igate(ull* re, ull* im, const ull* K) {
    const ull K0 = K[0], K1 = K[1], K2 = K[2], K3 = K[3], K4 = K[4], K5 = K[5];
#pragma unroll
    for (int m = 0; m < 8; m++) {
        const ull r = re[m], i = im[m];
        const ull rs = swap2(r), is = swap2(i);
        re[m] = f2fma(K5, is, f2fma(K3, rs, f2fma(K2, i, f2mul(K0, r))));
        im[m] = f2fma(K4, rs, f2fma(K3, is, f2fma(K1, r, f2mul(K0, i))));
    }
}

__device__ __forceinline__ float2 cmul(float2 a, float2 b) {
    return make_float2(a.x * b.x - a.y * b.y, a.x * b.y + a.y * b.x);
}

// ---------------------------------------------------------------------------
__global__ void __launch_bounds__(TPB, 1)
qsim_kernel(const float* __restrict__ xin, float* __restrict__ out) {
    extern __shared__ ull sm8[];                  // NSITE sites, 16B: {rre, rim}
    float* const smf = (float*)sm8;               // scalar view for gathers
    __shared__ ull      gpkS[NL][13][12];
    __shared__ ull      ginS[NL][6];
    __shared__ unsigned qfS[NL][NQ];
    __shared__ float2   rxf[NQ];
    __shared__ float    red[TPB / 32];

    const int t = threadIdx.x;                    // 0..1023
    const int b = blockIdx.x;

    for (int i = t; i < NL * 13 * 12; i += TPB) ((ull*)gpkS)[i] = ((const ull*)d_gpk)[i];
    if (t < NL * 6)  ((ull*)ginS)[t] = ((const ull*)d_gin)[t];
    if (t < NL * NQ) ((unsigned*)qfS)[t] = ((const unsigned*)d_qf)[t];
    if (t < NQ) {
        float c, sn;
        sincosf(0.5f * xin[b * NQ + t], &sn, &c);
        rxf[t] = make_float2(c, sn);
    }
    __syncthreads();

    ull rre[8], rim[8];

    // ---- init: RX product state in pass-A register layout ----
    // site z = t<<3 | m : wires 0-2 <- m, wires 3-12 <- t bits 0-9, pack = wire 13
    {
        float2 pre = make_float2(1.f, 0.f);
#pragma unroll
        for (int k = 0; k < 10; k++) {
            const float2 f = ((t >> k) & 1) ? make_float2(0.f, -rxf[3 + k].y)
                                            : make_float2(rxf[3 + k].x, 0.f);
            pre = cmul(pre, f);
        }
        const float c13 = rxf[13].x, s13 = rxf[13].y;
#pragma unroll
        for (int m = 0; m < 8; m++) {
            float2 v = pre;
#pragma unroll
            for (int k = 0; k < 3; k++) {
                const float2 f = ((m >> k) & 1) ? make_float2(0.f, -rxf[k].y)
                                                : make_float2(rxf[k].x, 0.f);
                v = cmul(v, f);
            }
            rre[m] = pk2(v.x * c13,  v.y * s13);
            rim[m] = pk2(v.y * c13, -v.x * s13);
        }
    }

    for (int l = 0; l < NL; l++) {
        // ===== Pass A: wires 0-2 (pack bits) + wire-13 intra; read = gather(prev perm)
        if (l > 0) {
            const unsigned* qm = qfS[l - 1];
            unsigned base = 0;
#pragma unroll
            for (int k = 0; k < 10; k++)
                if ((t >> k) & 1) base ^= qm[3 + k];
            const unsigned M0 = qm[0], M1 = qm[1], M2 = qm[2], M13 = qm[13];
#pragma unroll
            for (int m = 0; m < 8; m++) {
                unsigned u = base;
                if (m & 1) u ^= M0;
                if (m & 2) u ^= M1;
                if (m & 4) u ^= M2;
                const unsigned v = u ^ M13;
                rre[m] = pk2(smf[u],     smf[v]);
                rim[m] = pk2(smf[u ^ 2], smf[v ^ 2]);
            }
        }
        pgate<0>(rre, rim, gpkS[l][0]);
        pgate<1>(rre, rim, gpkS[l][1]);
        pgate<2>(rre, rim, gpkS[l][2]);
        igate(rre, rim, ginS[l]);
        if (l > 0) __syncthreads();               // gather reads done before overwrite
#pragma unroll
        for (int m = 0; m < 8; m++) {
            const unsigned z = ((unsigned)t << 3) | (unsigned)m;
            *(ulonglong2*)(sm8 + 2 * psite(z)) = make_ulonglong2(rre[m], rim[m]);
        }
        __syncthreads();

        // ===== Pass B: wires 3-5 (z bits 3-5)
#pragma unroll
        for (int m = 0; m < 8; m++) {
            const unsigned z = ((unsigned)t & 7) | ((unsigned)m << 3) | (((unsigned)t >> 3) << 6);
            const ulonglong2 v = *(const ulonglong2*)(sm8 + 2 * psite(z));
            rre[m] = v.x; rim[m] = v.y;
        }
        pgate<0>(rre, rim, gpkS[l][3]);
        pgate<1>(rre, rim, gpkS[l][4]);
        pgate<2>(rre, rim, gpkS[l][5]);
#pragma unroll
        for (int m = 0; m < 8; m++) {
            const unsigned z = ((unsigned)t & 7) | ((unsigned)m << 3) | (((unsigned)t >> 3) << 6);
            *(ulonglong2*)(sm8 + 2 * psite(z)) = make_ulonglong2(rre[m], rim[m]);
        }
        __syncthreads();

        // ===== Pass C: wires 6-8 (z bits 6-8)
#pragma unroll
        for (int m = 0; m < 8; m++) {
            const unsigned z = ((unsigned)t & 63) | ((unsigned)m << 6) | (((unsigned)t >> 6) << 9);
            const ulonglong2 v = *(const ulonglong2*)(sm8 + 2 * psite(z));
            rre[m] = v.x; rim[m] = v.y;
        }
        pgate<0>(rre, rim, gpkS[l][6]);
        pgate<1>(rre, rim, gpkS[l][7]);
        pgate<2>(rre, rim, gpkS[l][8]);
#pragma unroll
        for (int m = 0; m < 8; m++) {
            const unsigned z = ((unsigned)t & 63) | ((unsigned)m << 6) | (((unsigned)t >> 6) << 9);
            *(ulonglong2*)(sm8 + 2 * psite(z)) = make_ulonglong2(rre[m], rim[m]);
        }
        __syncthreads();

        // ===== Pass D: wires 9-11 (z bits 9-11)
#pragma unroll
        for (int m = 0; m < 8; m++) {
            const unsigned z = ((unsigned)t & 511) | ((unsigned)m << 9) | (((unsigned)t >> 9) << 12);
            const ulonglong2 v = *(const ulonglong2*)(sm8 + 2 * psite(z));
            rre[m] = v.x; rim[m] = v.y;
        }
        pgate<0>(rre, rim, gpkS[l][9]);
        pgate<1>(rre, rim, gpkS[l][10]);
        pgate<2>(rre, rim, gpkS[l][11]);
#pragma unroll
        for (int m = 0; m < 8; m++) {
            const unsigned z = ((unsigned)t & 511) | ((unsigned)m << 9) | (((unsigned)t >> 9) << 12);
            *(ulonglong2*)(sm8 + 2 * psite(z)) = make_ulonglong2(rre[m], rim[m]);
        }
        __syncthreads();

        // ===== Pass E: wire 12 (z bit 12 = m bit 2)
#pragma unroll
        for (int m = 0; m < 8; m++) {
            const unsigned z = (unsigned)t | ((unsigned)m << 10);
            const ulonglong2 v = *(const ulonglong2*)(sm8 + 2 * psite(z));
            rre[m] = v.x; rim[m] = v.y;
        }
        pgate<2>(rre, rim, gpkS[l][12]);
#pragma unroll
        for (int m = 0; m < 8; m++) {
            const unsigned z = (unsigned)t | ((unsigned)m << 10);
            *(ulonglong2*)(sm8 + 2 * psite(z)) = make_ulonglong2(rre[m], rim[m]);
        }
        __syncthreads();
    }

    // ---- reduction: fold last CNOT-ring perm as gather; <Z0> sign = m bit 0 ----
    {
        const unsigned* qm = qfS[NL - 1];
        unsigned base = 0;
#pragma unroll
        for (int k = 0; k < 10; k++)
            if ((t >> k) & 1) base ^= qm[3 + k];
        const unsigned M0 = qm[0], M1 = qm[1], M2 = qm[2], M13 = qm[13];
        float acc = 0.f;
#pragma unroll
        for (int m = 0; m < 8; m++) {
            unsigned u = base;
            if (m & 1) u ^= M0;
            if (m & 2) u ^= M1;
            if (m & 4) u ^= M2;
            const unsigned v = u ^ M13;
            const float re0 = smf[u],     im0 = smf[u ^ 2];
            const float re1 = smf[v],     im1 = smf[v ^ 2];
            const float p = re0 * re0 + im0 * im0 + re1 * re1 + im1 * im1;
            acc += (m & 1) ? -p : p;
        }
#pragma unroll
        for (int off = 16; off; off >>= 1)
            acc += __shfl_xor_sync(0xFFFFFFFFu, acc, off);
        if ((t & 31) == 0) red[t >> 5] = acc;
        __syncthreads();
        if (t == 0) {
            float tot = 0.f;
#pragma unroll
            for (int i = 0; i < TPB / 32; i++) tot += red[i];
            out[b] = tot;
        }
    }
}

extern "C" void kernel_launch(void* const* d_in, const int* in_sizes, int n_in,
                              void* d_out, int out_size) {
    const float* x = (const float*)d_in[0];       // (1024, 14)
    const float* w = (const float*)d_in[1];       // (6, 14, 3)
    float* out = (float*)d_out;                   // (1024,)

    cudaFuncSetAttribute(qsim_kernel,
                         cudaFuncAttributeMaxDynamicSharedMemorySize,
                         NSITE * 16);

    setup_kernel<<<1, 256>>>(w);
    qsim_kernel<<<BATCH, TPB, NSITE * 16>>>(x, out);
}

// round 15
// speedup vs baseline: 1.2824x; 1.2824x over previous
#include <cuda_runtime.h>

#define NQ    14
#define NL    6
#define BATCH 1024
#define NSITE 8192            // 2^13 sites (pack dim = wire 0), 16B each {RR, II}
#define TPB   512

typedef unsigned long long ull;

// ---------------- f32x2 packed helpers ----------------
__device__ __forceinline__ ull f2mul(ull a, ull b) {
    ull d; asm("mul.rn.f32x2 %0,%1,%2;" : "=l"(d) : "l"(a), "l"(b)); return d;
}
__device__ __forceinline__ ull f2fma(ull a, ull b, ull c) {
    ull d; asm("fma.rn.f32x2 %0,%1,%2,%3;" : "=l"(d) : "l"(a), "l"(b), "l"(c)); return d;
}
__device__ __forceinline__ ull pk2(float lo, float hi) {
    ull d; asm("mov.b64 %0,{%1,%2};" : "=l"(d) : "f"(lo), "f"(hi)); return d;
}
__device__ __forceinline__ ull dup2(float v) {
    ull d; asm("mov.b64 %0,{%1,%1};" : "=l"(d) : "f"(v)); return d;
}
__device__ __forceinline__ ull swap2(ull v) {
    ull d;
    asm("{ .reg .b32 lo,hi; mov.b64 {lo,hi},%1; mov.b64 %0,{hi,lo}; }"
        : "=l"(d) : "l"(v));
    return d;
}

// ---------------- layout maps (GF(2)-linear) ----------------
// site z (13 bits = wires 1..13) -> physical site: low-3 bits get z[4:6] XORed in
__host__ __device__ __forceinline__ unsigned psite(unsigned z) {
    return z ^ ((z >> 4) & 7u);
}
// 14-bit state x -> physical float index of Re(amp): site*4 | wire0 ; Im = +2
__host__ __device__ __forceinline__ unsigned famp(unsigned x) {
    return (psite(x >> 1) << 2) | (x & 1u);
}

// ---------------- precomputed tables ----------------
// d_gpk[l][w-1][12] for wires w=1..13 (duplicated packed coeffs)
// d_gin[l][6]: intra-pack (wire 0) paired coeffs
// d_qf[l][14]: CNOT-ring perm columns pre-mapped to PHYSICAL float-index space
__device__ ull      d_gpk[NL][13][12];
__device__ ull      d_gin[NL][6];
__device__ unsigned d_qf[NL][NQ];

__global__ void setup_kernel(const float* __restrict__ w) {
    const int tid = threadIdx.x;
    if (tid < NL * NQ) {
        const int l = tid / NQ, q = tid % NQ;
        const float phi = w[tid * 3 + 0];
        const float th  = w[tid * 3 + 1];
        const float om  = w[tid * 3 + 2];
        float cth, sth, ca, sa, cb, sb;
        sincosf(0.5f * th, &sth, &cth);
        sincosf(0.5f * (phi + om), &sa, &ca);
        sincosf(0.5f * (phi - om), &sb, &cb);
        // Rot = RZ(om) RY(th) RZ(phi)
        const float g00r =  cth * ca, g00i = -cth * sa;
        const float g01r = -sth * cb, g01i = -sth * sb;
        const float g10r =  sth * cb, g10i = -sth * sb;
        const float g11r =  cth * ca, g11i =  cth * sa;
        if (q > 0) {
            ull* g = d_gpk[l][q - 1];
            g[0]  = dup2(g00r); g[1]  = dup2(g00i); g[2]  = dup2(-g00i);
            g[3]  = dup2(g01r); g[4]  = dup2(g01i); g[5]  = dup2(-g01i);
            g[6]  = dup2(g10r); g[7]  = dup2(g10i); g[8]  = dup2(-g10i);
            g[9]  = dup2(g11r); g[10] = dup2(g11i); g[11] = dup2(-g11i);
        } else {
            ull* K = d_gin[l];
            K[0] = pk2(g00r, g11r);  K[1] = pk2(g00i, g11i);
            K[2] = pk2(-g00i, -g11i);
            K[3] = pk2(g01r, g10r);  K[4] = pk2(g01i, g10i);
            K[5] = pk2(-g01i, -g10i);
        }
    } else if (tid >= 128 && tid < 128 + NL * NQ) {
        const int id = tid - 128;
        const int l = id / NQ, b = id % NQ;
        const int rr = (l % (NQ - 1)) + 1;
        unsigned y = 1u << b;
        for (int ww = NQ - 1; ww >= 0; ww--) {
            const unsigned bit = (y >> ww) & 1u;
            y ^= bit << ((ww + rr) % NQ);
        }
        d_qf[l][b] = famp(y);
    }
}

// ---------------- packed 2x2 gate on site-block bit P (16 sites) ----------------
template <int P>
__device__ __forceinline__ void pgate(ull* re, ull* im, const ull* gg) {
    const ull g0 = gg[0], g1 = gg[1], g2 = gg[2], g3 = gg[3], g4 = gg[4], g5 = gg[5];
    const ull g6 = gg[6], g7 = gg[7], g8 = gg[8], g9 = gg[9], g10 = gg[10], g11 = gg[11];
#pragma unroll
    for (int base = 0; base < 16; base++) {
        if (base & (1 << P)) continue;
        const int hi = base | (1 << P);
        const ull are = re[base], aim = im[base], bre = re[hi], bim = im[hi];
        re[base] = f2fma(g5,  bim, f2fma(g3, bre, f2fma(g2, aim, f2mul(g0, are))));
        im[base] = f2fma(g4,  bre, f2fma(g3, bim, f2fma(g1, are, f2mul(g0, aim))));
        re[hi]   = f2fma(g11, bim, f2fma(g9, bre, f2fma(g8, aim, f2mul(g6, are))));
        im[hi]   = f2fma(g10, bre, f2fma(g9, bim, f2fma(g7, are, f2mul(g6, aim))));
    }
}

// intra-pack gate (pack dimension = wire 0), 16 sites
__device__ __forceinline__ void igate(ull* re, ull* im, const ull* K) {
    const ull K0 = K[0], K1 = K[1], K2 = K[2], K3 = K[3], K4 = K[4], K5 = K[5];
#pragma unroll
    for (int m = 0; m < 16; m++) {
        const ull r = re[m], i = im[m];
        const ull rs = swap2(r), is = swap2(i);
        re[m] = f2fma(K5, is, f2fma(K3, rs, f2fma(K2, i, f2mul(K0, r))));
        im[m] = f2fma(K4, rs, f2fma(K3, is, f2fma(K1, r, f2mul(K0, i))));
    }
}

__device__ __forceinline__ float2 cmul(float2 a, float2 b) {
    return make_float2(a.x * b.x - a.y * b.y, a.x * b.y + a.y * b.x);
}

// ---------------------------------------------------------------------------
__global__ void __launch_bounds__(TPB, 1)
qsim_kernel(const float* __restrict__ xin, float* __restrict__ out) {
    extern __shared__ ull sm8[];                  // NSITE sites, 16B: {RR, II}
    float* const smf = (float*)sm8;               // scalar view for gathers
    __shared__ ull      gpkS[NL][13][12];
    __shared__ ull      ginS[NL][6];
    __shared__ unsigned qfS[NL][NQ];
    __shared__ float2   rxf[NQ];
    __shared__ float    red[TPB / 32];

    const int t = threadIdx.x;                    // 0..511 (x bits 5..13)
    const int b = blockIdx.x;

    for (int i = t; i < NL * 13 * 12; i += TPB) ((ull*)gpkS)[i] = ((const ull*)d_gpk)[i];
    if (t < NL * 6)  ((ull*)ginS)[t] = ((const ull*)d_gin)[t];
    if (t < NL * NQ) ((unsigned*)qfS)[t] = ((const unsigned*)d_qf)[t];
    if (t < NQ) {
        float c, sn;
        sincosf(0.5f * xin[b * NQ + t], &sn, &c);
        rxf[t] = make_float2(c, sn);
    }
    __syncthreads();

    ull rre[16], rim[16];

    // ---- init: RX product state in pass-1 register layout ----
    // site z = t<<4 | m : wires 1-4 <- m, wires 5-13 <- t bits 0-8, lane = wire 0
    {
        float2 pre = make_float2(1.f, 0.f);
#pragma unroll
        for (int k = 0; k < 9; k++) {
            const float2 f = ((t >> k) & 1) ? make_float2(0.f, -rxf[5 + k].y)
                                            : make_float2(rxf[5 + k].x, 0.f);
            pre = cmul(pre, f);
        }
        const float c0 = rxf[0].x, s0 = rxf[0].y;
#pragma unroll
        for (int m = 0; m < 16; m++) {
            float2 v = pre;
#pragma unroll
            for (int k = 0; k < 4; k++) {
                const float2 f = ((m >> k) & 1) ? make_float2(0.f, -rxf[1 + k].y)
                                                : make_float2(rxf[1 + k].x, 0.f);
                v = cmul(v, f);
            }
            // amp(w0=0) = v*(c0,0); amp(w0=1) = v*(0,-s0)
            rre[m] = pk2(v.x * c0,  v.y * s0);
            rim[m] = pk2(v.y * c0, -v.x * s0);
        }
    }

    for (int l = 0; l < NL; l++) {
        // ===== Pass 1: wire 0 intra + wires 1-4 (z bits 0-3); read = gather(prev perm)
        if (l > 0) {
            const unsigned* qm = qfS[l - 1];
            unsigned base = 0;
#pragma unroll
            for (int k = 0; k < 9; k++)
                if ((t >> k) & 1) base ^= qm[5 + k];
            const unsigned M1 = qm[1], M2 = qm[2], M3 = qm[3], M4 = qm[4], M0 = qm[0];
#pragma unroll
            for (int m = 0; m < 16; m++) {
                unsigned u = base;
                if (m & 1) u ^= M1;
                if (m & 2) u ^= M2;
                if (m & 4) u ^= M3;
                if (m & 8) u ^= M4;
                const unsigned v = u ^ M0;        // lane-1 amp (wire0 flipped)
                rre[m] = pk2(smf[u],     smf[v]);
                rim[m] = pk2(smf[u ^ 2], smf[v ^ 2]);
            }
        }
        igate(rre, rim, ginS[l]);                 // wire 0
        pgate<0>(rre, rim, gpkS[l][0]);           // wire 1
        pgate<1>(rre, rim, gpkS[l][1]);           // wire 2
        pgate<2>(rre, rim, gpkS[l][2]);           // wire 3
        pgate<3>(rre, rim, gpkS[l][3]);           // wire 4
        if (l > 0) __syncthreads();               // gather reads done before overwrite
#pragma unroll
        for (int m = 0; m < 16; m++) {
            const unsigned z = ((unsigned)t << 4) | (unsigned)m;
            *(ulonglong2*)(sm8 + 2 * psite(z)) = make_ulonglong2(rre[m], rim[m]);
        }
        __syncthreads();

        // ===== Pass 2: wires 5-8 (z bits 4-7)
#pragma unroll
        for (int m = 0; m < 16; m++) {
            const unsigned z = (((unsigned)t >> 4) << 8) | ((unsigned)m << 4) | ((unsigned)t & 15);
            const ulonglong2 v = *(const ulonglong2*)(sm8 + 2 * psite(z));
            rre[m] = v.x; rim[m] = v.y;
        }
        pgate<0>(rre, rim, gpkS[l][4]);
        pgate<1>(rre, rim, gpkS[l][5]);
        pgate<2>(rre, rim, gpkS[l][6]);
        pgate<3>(rre, rim, gpkS[l][7]);
#pragma unroll
        for (int m = 0; m < 16; m++) {
            const unsigned z = (((unsigned)t >> 4) << 8) | ((unsigned)m << 4) | ((unsigned)t & 15);
            *(ulonglong2*)(sm8 + 2 * psite(z)) = make_ulonglong2(rre[m], rim[m]);
        }
        __syncthreads();

        // ===== Pass 3: wires 9-12 (z bits 8-11)
#pragma unroll
        for (int m = 0; m < 16; m++) {
            const unsigned z = (((unsigned)t >> 8) << 12) | ((unsigned)m << 8) | ((unsigned)t & 255);
            const ulonglong2 v = *(const ulonglong2*)(sm8 + 2 * psite(z));
            rre[m] = v.x; rim[m] = v.y;
        }
        pgate<0>(rre, rim, gpkS[l][8]);
        pgate<1>(rre, rim, gpkS[l][9]);
        pgate<2>(rre, rim, gpkS[l][10]);
        pgate<3>(rre, rim, gpkS[l][11]);
#pragma unroll
        for (int m = 0; m < 16; m++) {
            const unsigned z = (((unsigned)t >> 8) << 12) | ((unsigned)m << 8) | ((unsigned)t & 255);
            *(ulonglong2*)(sm8 + 2 * psite(z)) = make_ulonglong2(rre[m], rim[m]);
        }
        __syncthreads();

        // ===== Pass 4: wire 13 (z bit 12 = m bit 3)
#pragma unroll
        for (int m = 0; m < 16; m++) {
            const unsigned z = ((unsigned)t & 7) | (((unsigned)m & 7) << 3)
                             | (((unsigned)t >> 3) << 6) | (((unsigned)m >> 3) << 12);
            const ulonglong2 v = *(const ulonglong2*)(sm8 + 2 * psite(z));
            rre[m] = v.x; rim[m] = v.y;
        }
        pgate<3>(rre, rim, gpkS[l][12]);
#pragma unroll
        for (int m = 0; m < 16; m++) {
            const unsigned z = ((unsigned)t & 7) | (((unsigned)m & 7) << 3)
                             | (((unsigned)t >> 3) << 6) | (((unsigned)m >> 3) << 12);
            *(ulonglong2*)(sm8 + 2 * psite(z)) = make_ulonglong2(rre[m], rim[m]);
        }
        __syncthreads();
    }

    // ---- reduction: fold last CNOT-ring perm as gather; <Z0> sign = wire-0 lane ----
    {
        const unsigned* qm = qfS[NL - 1];
        unsigned base = 0;
#pragma unroll
        for (int k = 0; k < 9; k++)
            if ((t >> k) & 1) base ^= qm[5 + k];
        const unsigned M1 = qm[1], M2 = qm[2], M3 = qm[3], M4 = qm[4], M0 = qm[0];
        float acc = 0.f;
#pragma unroll
        for (int m = 0; m < 16; m++) {
            unsigned u = base;
            if (m & 1) u ^= M1;
            if (m & 2) u ^= M2;
            if (m & 4) u ^= M3;
            if (m & 8) u ^= M4;
            const unsigned v = u ^ M0;
            const float re0 = smf[u],     im0 = smf[u ^ 2];
            const float re1 = smf[v],     im1 = smf[v ^ 2];
            acc += (re0 * re0 + im0 * im0) - (re1 * re1 + im1 * im1);
        }
#pragma unroll
        for (int off = 16; off; off >>= 1)
            acc += __shfl_xor_sync(0xFFFFFFFFu, acc, off);
        if ((t & 31) == 0) red[t >> 5] = acc;
        __syncthreads();
        if (t == 0) {
            float tot = 0.f;
#pragma unroll
            for (int i = 0; i < TPB / 32; i++) tot += red[i];
            out[b] = tot;
        }
    }
}

extern "C" void kernel_launch(void* const* d_in, const int* in_sizes, int n_in,
                              void* d_out, int out_size) {
    const float* x = (const float*)d_in[0];       // (1024, 14)
    const float* w = (const float*)d_in[1];       // (6, 14, 3)
    float* out = (float*)d_out;                   // (1024,)

    cudaFuncSetAttribute(qsim_kernel,
                         cudaFuncAttributeMaxDynamicSharedMemorySize,
                         NSITE * 16);

    setup_kernel<<<1, 256>>>(w);
    qsim_kernel<<<BATCH, TPB, NSITE * 16>>>(x, out);
}